// round 2
// baseline (speedup 1.0000x reference)
#include <cuda_runtime.h>
#include <math.h>

// Problem constants (B=8, L=4096, D=1024, fp32)
#define BB 8
#define LL 4096
#define DD 1024
#define ND (LL - 1)   // 4095 deltas per batch row
#define NI (LL - 2)   // 4094 delta_increase terms per batch
#define TCHUNK 16     // deltas computed per block (reads TCHUNK+1 rows)

// Scratch for per-(b,t) L2 norms of row diffs. Static device array (no allocs).
__device__ float g_deltas[BB * ND];

// Kernel 1: deltas[b,t] = || states[b,t+1,:] - states[b,t,:] ||_2
// Block = 256 threads, each holds one float4 (256*4 = 1024 = D).
// Each block covers TCHUNK consecutive t for one b, carrying the previous
// row in registers so each states row is loaded ~once (17 rows / 16 deltas).
__global__ __launch_bounds__(256) void deltas_kernel(const float* __restrict__ states) {
    const int b  = blockIdx.y;
    const int t0 = blockIdx.x * TCHUNK;
    const int tid = threadIdx.x;

    const float4* __restrict__ base =
        reinterpret_cast<const float4*>(states + (size_t)b * LL * DD);
    // row r occupies float4 indices [r*256, r*256+256)

    float4 prev = base[(size_t)t0 * 256 + tid];

    __shared__ float warp_sums[8];

    #pragma unroll
    for (int i = 0; i < TCHUNK; i++) {
        const int t = t0 + i;
        if (t >= ND) break;
        float4 cur = base[(size_t)(t + 1) * 256 + tid];
        float dx = cur.x - prev.x;
        float dy = cur.y - prev.y;
        float dz = cur.z - prev.z;
        float dw = cur.w - prev.w;
        float s = dx * dx + dy * dy + dz * dz + dw * dw;

        // warp reduce
        #pragma unroll
        for (int o = 16; o > 0; o >>= 1)
            s += __shfl_xor_sync(0xffffffffu, s, o);
        if ((tid & 31) == 0) warp_sums[tid >> 5] = s;
        __syncthreads();
        if (tid < 8) {
            float v = warp_sums[tid];
            #pragma unroll
            for (int o = 4; o > 0; o >>= 1)
                v += __shfl_xor_sync(0xffu, v, o);
            if (tid == 0) g_deltas[b * ND + t] = sqrtf(v);
        }
        __syncthreads();   // protect warp_sums for next iteration
        prev = cur;
    }
}

// Kernel 2: final scalar loss.
//   delta_increase[b,t] = relu(deltas[b,t+1] - deltas[b,t]),  t in [0, NI)
//   mask[b,t]           = reasoning_mask[b, t+2]
//   dist                = max(rtp[b] - t - 2, 0)
//   w                   = dist < 5 ? 2 + (5-dist)*0.5 : 1
//   out = sum(di * mask * w) / (sum(mask) + 1e-9)
//
// rtp dtype hedge: the reference asks for int64 but (depending on the
// framework config) may deliver int32. We read the buffer as 16 int32
// words. Little-endian int64 values < 4096 => all odd words are zero
// => take even words; otherwise treat as int32 and take words directly.
__global__ __launch_bounds__(256) void loss_kernel(const float* __restrict__ reasoning_mask,
                                                   const int* __restrict__ rtp_raw,
                                                   float* __restrict__ out) {
    const int tid = threadIdx.x;

    __shared__ int s_rtp[BB];
    if (tid == 0) {
        int odd_or = 0;
        #pragma unroll
        for (int i = 1; i < 16; i += 2) odd_or |= rtp_raw[i];
        const bool is64 = (odd_or == 0);
        #pragma unroll
        for (int b = 0; b < BB; b++)
            s_rtp[b] = is64 ? rtp_raw[2 * b] : rtp_raw[b];
    }
    __syncthreads();

    float ws = 0.0f, ms = 0.0f;

    for (int idx = tid; idx < BB * NI; idx += 256) {
        const int b = idx / NI;
        const int t = idx - b * NI;
        float di = g_deltas[b * ND + t + 1] - g_deltas[b * ND + t];
        di = fmaxf(di, 0.0f);
        const float m = reasoning_mask[b * LL + t + 2];
        int dist = s_rtp[b] - t - 2;
        if (dist < 0) dist = 0;
        const float w = (dist < 5) ? (2.0f + (float)(5 - dist) * 0.5f) : 1.0f;
        ws += di * m * w;
        ms += m;
    }

    // block reduce (two values)
    __shared__ float s_ws[8], s_ms[8];
    #pragma unroll
    for (int o = 16; o > 0; o >>= 1) {
        ws += __shfl_xor_sync(0xffffffffu, ws, o);
        ms += __shfl_xor_sync(0xffffffffu, ms, o);
    }
    if ((tid & 31) == 0) { s_ws[tid >> 5] = ws; s_ms[tid >> 5] = ms; }
    __syncthreads();
    if (tid < 8) {
        float vws = s_ws[tid];
        float vms = s_ms[tid];
        #pragma unroll
        for (int o = 4; o > 0; o >>= 1) {
            vws += __shfl_xor_sync(0xffu, vws, o);
            vms += __shfl_xor_sync(0xffu, vms, o);
        }
        if (tid == 0) out[0] = vws / (vms + 1e-9f);
    }
}

extern "C" void kernel_launch(void* const* d_in, const int* in_sizes, int n_in,
                              void* d_out, int out_size) {
    const float* states = (const float*)d_in[0];
    const float* rmask  = (const float*)d_in[1];
    const int*   rtp    = (const int*)d_in[2];
    float*       out    = (float*)d_out;

    dim3 grid((ND + TCHUNK - 1) / TCHUNK, BB);   // (256, 8)
    deltas_kernel<<<grid, 256>>>(states);
    loss_kernel<<<1, 256>>>(rmask, rtp, out);
}

// round 3
// speedup vs baseline: 2.6871x; 2.6871x over previous
#include <cuda_runtime.h>
#include <math.h>

// Problem constants (B=8, L=4096, D=1024, fp32)
#define BB 8
#define LL 4096
#define DD 1024
#define ND (LL - 1)   // 4095 deltas per batch row
#define NI (LL - 2)   // 4094 delta_increase terms per batch
#define TCHUNK 16     // deltas computed per block (reads TCHUNK+1 rows)

// Scratch + accumulators. Static device arrays (no allocs).
__device__ float g_deltas[BB * ND];
__device__ float g_ws;
__device__ float g_ms;

// Kernel 1: deltas[b,t] = || states[b,t+1,:] - states[b,t,:] ||_2
// Block = 256 threads, each holds one float4 (256*4 = 1024 = D).
// Each block covers TCHUNK consecutive t for one b, carrying the previous
// row in registers so each states row is loaded ~once (17 rows / 16 deltas).
// Block (0,0) thread 0 also zeroes the loss accumulators (safe: the loss
// kernel is a later launch in the same stream).
__global__ __launch_bounds__(256) void deltas_kernel(const float* __restrict__ states) {
    const int b  = blockIdx.y;
    const int t0 = blockIdx.x * TCHUNK;
    const int tid = threadIdx.x;

    if (blockIdx.x == 0 && blockIdx.y == 0 && tid == 0) {
        g_ws = 0.0f;
        g_ms = 0.0f;
    }

    const float4* __restrict__ base =
        reinterpret_cast<const float4*>(states + (size_t)b * LL * DD);

    float4 prev = base[(size_t)t0 * 256 + tid];

    __shared__ float warp_sums[8];

    #pragma unroll
    for (int i = 0; i < TCHUNK; i++) {
        const int t = t0 + i;
        if (t >= ND) break;
        float4 cur = base[(size_t)(t + 1) * 256 + tid];
        float dx = cur.x - prev.x;
        float dy = cur.y - prev.y;
        float dz = cur.z - prev.z;
        float dw = cur.w - prev.w;
        float s = dx * dx + dy * dy + dz * dz + dw * dw;

        #pragma unroll
        for (int o = 16; o > 0; o >>= 1)
            s += __shfl_xor_sync(0xffffffffu, s, o);
        if ((tid & 31) == 0) warp_sums[tid >> 5] = s;
        __syncthreads();
        if (tid < 8) {
            float v = warp_sums[tid];
            #pragma unroll
            for (int o = 4; o > 0; o >>= 1)
                v += __shfl_xor_sync(0xffu, v, o);
            if (tid == 0) g_deltas[b * ND + t] = sqrtf(v);
        }
        __syncthreads();   // protect warp_sums for next iteration
        prev = cur;
    }
}

// Kernel 2: grid-parallel weighted reduction.
// Grid (16, 8) x 256 threads: thread handles exactly one (b, t) element.
//   delta_increase[b,t] = relu(deltas[b,t+1] - deltas[b,t]),  t in [0, NI)
//   mask[b,t]           = reasoning_mask[b, t+2]
//   dist                = max(rtp[b] - t - 2, 0)
//   w                   = dist < 5 ? 2 + (5-dist)*0.5 : 1
// One atomicAdd per block into g_ws / g_ms.
//
// rtp dtype hedge: buffer may be int64 or int32. Read as 16 int32 words;
// little-endian int64 values < 4096 => all odd words zero => take even words.
__global__ __launch_bounds__(256) void loss_kernel(const float* __restrict__ reasoning_mask,
                                                   const int* __restrict__ rtp_raw) {
    const int tid = threadIdx.x;
    const int b = blockIdx.y;
    const int t = blockIdx.x * 256 + tid;

    // Decode this batch's rtp (cheap, uniform within block).
    int odd_or = 0;
    #pragma unroll
    for (int i = 1; i < 16; i += 2) odd_or |= rtp_raw[i];
    const int rtp_b = (odd_or == 0) ? rtp_raw[2 * b] : rtp_raw[b];

    float ws = 0.0f, ms = 0.0f;
    if (t < NI) {
        float di = g_deltas[b * ND + t + 1] - g_deltas[b * ND + t];
        di = fmaxf(di, 0.0f);
        const float m = reasoning_mask[b * LL + t + 2];
        int dist = rtp_b - t - 2;
        if (dist < 0) dist = 0;
        const float w = (dist < 5) ? (2.0f + (float)(5 - dist) * 0.5f) : 1.0f;
        ws = di * m * w;
        ms = m;
    }

    // block reduce (two values)
    __shared__ float s_ws[8], s_ms[8];
    #pragma unroll
    for (int o = 16; o > 0; o >>= 1) {
        ws += __shfl_xor_sync(0xffffffffu, ws, o);
        ms += __shfl_xor_sync(0xffffffffu, ms, o);
    }
    if ((tid & 31) == 0) { s_ws[tid >> 5] = ws; s_ms[tid >> 5] = ms; }
    __syncthreads();
    if (tid < 8) {
        float vws = s_ws[tid];
        float vms = s_ms[tid];
        #pragma unroll
        for (int o = 4; o > 0; o >>= 1) {
            vws += __shfl_xor_sync(0xffu, vws, o);
            vms += __shfl_xor_sync(0xffu, vms, o);
        }
        if (tid == 0) {
            atomicAdd(&g_ws, vws);
            atomicAdd(&g_ms, vms);
        }
    }
}

// Kernel 3: finalize.
__global__ void finalize_kernel(float* __restrict__ out) {
    out[0] = g_ws / (g_ms + 1e-9f);
}

extern "C" void kernel_launch(void* const* d_in, const int* in_sizes, int n_in,
                              void* d_out, int out_size) {
    const float* states = (const float*)d_in[0];
    const float* rmask  = (const float*)d_in[1];
    const int*   rtp    = (const int*)d_in[2];
    float*       out    = (float*)d_out;

    dim3 grid1((ND + TCHUNK - 1) / TCHUNK, BB);   // (256, 8)
    deltas_kernel<<<grid1, 256>>>(states);

    dim3 grid2((NI + 255) / 256, BB);             // (16, 8)
    loss_kernel<<<grid2, 256>>>(rmask, rtp);

    finalize_kernel<<<1, 1>>>(out);
}

// round 4
// speedup vs baseline: 3.2146x; 1.1963x over previous
#include <cuda_runtime.h>
#include <math.h>

// Problem constants (B=8, L=4096, D=1024, fp32)
#define BB 8
#define LL 4096
#define DD 1024
#define ND (LL - 1)   // 4095 deltas per batch row
#define NI (LL - 2)   // 4094 delta_increase terms per batch
#define TCHUNK 16     // deltas computed per block (reads TCHUNK+1 rows)

// Scratch + accumulators. Static device arrays (no allocs).
__device__ float g_deltas[BB * ND];
__device__ float g_ws;
__device__ float g_ms;
__device__ unsigned int g_ticket;

// Kernel 1: deltas[b,t] = || states[b,t+1,:] - states[b,t,:] ||_2
// Block = 256 threads, each holds one float4 (256*4 = 1024 = D).
// Each block covers TCHUNK consecutive t for one b, carrying the previous
// row in registers. Inner loop is BARRIER-FREE: warp-level shfl reduce only,
// per-warp partials parked in smem; one barrier + tiny combine at the end.
// This lets all TCHUNK row loads be in flight simultaneously (high MLP).
__global__ __launch_bounds__(256) void deltas_kernel(const float* __restrict__ states) {
    const int b  = blockIdx.y;
    const int t0 = blockIdx.x * TCHUNK;
    const int tid  = threadIdx.x;
    const int warp = tid >> 5;

    if (blockIdx.x == 0 && blockIdx.y == 0 && tid == 0) {
        g_ws = 0.0f;
        g_ms = 0.0f;
        g_ticket = 0u;
    }

    const float4* __restrict__ base =
        reinterpret_cast<const float4*>(states + (size_t)b * LL * DD);

    __shared__ float warp_sums[TCHUNK][8];

    float4 prev = base[(size_t)t0 * 256 + tid];

    #pragma unroll
    for (int i = 0; i < TCHUNK; i++) {
        const int t = t0 + i;
        float s = 0.0f;
        float4 cur = prev;
        if (t < ND) {
            cur = base[(size_t)(t + 1) * 256 + tid];
            float dx = cur.x - prev.x;
            float dy = cur.y - prev.y;
            float dz = cur.z - prev.z;
            float dw = cur.w - prev.w;
            s = dx * dx + dy * dy + dz * dz + dw * dw;
        }
        // warp reduce (no block barrier)
        #pragma unroll
        for (int o = 16; o > 0; o >>= 1)
            s += __shfl_xor_sync(0xffffffffu, s, o);
        if ((tid & 31) == 0) warp_sums[i][warp] = s;
        prev = cur;
    }

    __syncthreads();

    if (tid < TCHUNK) {
        const int t = t0 + tid;
        if (t < ND) {
            float v = 0.0f;
            #pragma unroll
            for (int w = 0; w < 8; w++) v += warp_sums[tid][w];
            g_deltas[b * ND + t] = sqrtf(v);
        }
    }
}

// Kernel 2: grid-parallel weighted reduction + fused finalize.
// Grid (16, 8) x 256 threads: one (b, t) element per thread.
//   delta_increase[b,t] = relu(deltas[b,t+1] - deltas[b,t]),  t in [0, NI)
//   mask[b,t]           = reasoning_mask[b, t+2]
//   dist                = max(rtp[b] - t - 2, 0)
//   w                   = dist < 5 ? 2 + (5-dist)*0.5 : 1
// One atomicAdd per block into g_ws / g_ms; the LAST block (atomic ticket)
// reads the totals and writes out = ws / (ms + 1e-9).
//
// rtp dtype hedge: buffer may be int64 or int32. Read as 16 int32 words;
// little-endian int64 values < 4096 => all odd words zero => take even words.
__global__ __launch_bounds__(256) void loss_kernel(const float* __restrict__ reasoning_mask,
                                                   const int* __restrict__ rtp_raw,
                                                   float* __restrict__ out) {
    const int tid = threadIdx.x;
    const int b = blockIdx.y;
    const int t = blockIdx.x * 256 + tid;
    const unsigned int nblocks = gridDim.x * gridDim.y;

    int odd_or = 0;
    #pragma unroll
    for (int i = 1; i < 16; i += 2) odd_or |= rtp_raw[i];
    const int rtp_b = (odd_or == 0) ? rtp_raw[2 * b] : rtp_raw[b];

    float ws = 0.0f, ms = 0.0f;
    if (t < NI) {
        float di = g_deltas[b * ND + t + 1] - g_deltas[b * ND + t];
        di = fmaxf(di, 0.0f);
        const float m = reasoning_mask[b * LL + t + 2];
        int dist = rtp_b - t - 2;
        if (dist < 0) dist = 0;
        const float w = (dist < 5) ? (2.0f + (float)(5 - dist) * 0.5f) : 1.0f;
        ws = di * m * w;
        ms = m;
    }

    // block reduce (two values)
    __shared__ float s_ws[8], s_ms[8];
    #pragma unroll
    for (int o = 16; o > 0; o >>= 1) {
        ws += __shfl_xor_sync(0xffffffffu, ws, o);
        ms += __shfl_xor_sync(0xffffffffu, ms, o);
    }
    if ((tid & 31) == 0) { s_ws[tid >> 5] = ws; s_ms[tid >> 5] = ms; }
    __syncthreads();
    if (tid < 8) {
        float vws = s_ws[tid];
        float vms = s_ms[tid];
        #pragma unroll
        for (int o = 4; o > 0; o >>= 1) {
            vws += __shfl_xor_sync(0xffu, vws, o);
            vms += __shfl_xor_sync(0xffu, vms, o);
        }
        if (tid == 0) {
            atomicAdd(&g_ws, vws);
            atomicAdd(&g_ms, vms);
            __threadfence();
            const unsigned int my = atomicAdd(&g_ticket, 1u);
            if (my == nblocks - 1u) {
                // all other blocks' atomics are visible (L2-coherent + fence)
                out[0] = g_ws / (g_ms + 1e-9f);
            }
        }
    }
}

extern "C" void kernel_launch(void* const* d_in, const int* in_sizes, int n_in,
                              void* d_out, int out_size) {
    const float* states = (const float*)d_in[0];
    const float* rmask  = (const float*)d_in[1];
    const int*   rtp    = (const int*)d_in[2];
    float*       out    = (float*)d_out;

    dim3 grid1((ND + TCHUNK - 1) / TCHUNK, BB);   // (256, 8)
    deltas_kernel<<<grid1, 256>>>(states);

    dim3 grid2((NI + 255) / 256, BB);             // (16, 8)
    loss_kernel<<<grid2, 256>>>(rmask, rtp, out);
}